// round 5
// baseline (speedup 1.0000x reference)
#include <cuda_runtime.h>
#include <stdint.h>

// TDGSPooling2d: gumbel-softmax hard pooling over 2x2 patches (forward = argmax).
// out[b,c,ho,wo] = x_patch[argmax_k(x_patch[k]/temp[c,ho,wo] + g_k)]
// Noise: JAX partitionable threefry: bits[i] = o0^o1,
//   (o0,o1) = threefry2x32(key=(0,42), counter=(0,i))
//
// R5: threefry rotate moved off the alu pipe. rotl(v,r) = lo|hi of
// mul.wide.u32(v, 1<<r)  (IMAD.WIDE, fma pipe), and the round's
// "(rotl ^ x0)" collapses into ONE 3-input LOP3 ((lo|hi)^x0, lut 0x56).
// Per round: alu-pinned ops drop 2 -> 1; fma picks up the IMAD.WIDE.
// Exact integer identity -> noise bit-identical to previous rounds.

#define HALF_CNT 25690112u   // noise & x element offset between b and b+16
#define OUT_HALF 6422528u    // output element offset between b and b+16

// (rotl(v, r) ^ x0) with rotate on the FMA pipe:
//   w = v * 2^r (64-bit): lo = v<<r, hi = v>>(32-r)   [IMAD.WIDE.U32]
//   result = (lo | hi) ^ x0                            [single LOP3, lut 0x56]
__device__ __forceinline__ uint32_t rotxor(uint32_t v, uint32_t x0, int r) {
    unsigned long long w;
    uint32_t lo, hi, res;
    asm("mul.wide.u32 %0, %1, %2;" : "=l"(w) : "r"(v), "r"(1u << r));
    asm("mov.b64 {%0,%1}, %2;" : "=r"(lo), "=r"(hi) : "l"(w));  // reg-pair alias, free
    asm("lop3.b32 %0, %1, %2, %3, 0x56;" : "=r"(res) : "r"(lo), "r"(hi), "r"(x0));
    return res;
}

// ---------- threefry2x32, key=(0,42), counter (0,c1), return o0^o1 ----------
// ks0 = 0, ks1 = 42, ks2 = 0x1BD11BDA ^ 0 ^ 42 = 0x1BD11BF0
__device__ __forceinline__ uint32_t tf_xor_0_42(uint32_t c1) {
    const uint32_t ks1 = 42u;
    const uint32_t ks2 = 0x1BD11BF0u;
    uint32_t x1 = c1 + ks1;
    uint32_t x0 = x1;                 // round-1 add with x0 = c0+ks0 = 0
    x1 = rotxor(x1, x0, 13);
#define R(r) { x0 += x1; x1 = rotxor(x1, x0, (r)); }
    R(15) R(26) R(6)
    x0 += ks1;  x1 += ks2 + 1u;
    R(17) R(29) R(16) R(24)
    x0 += ks2;  x1 += 2u;                 // ks0 + 2
    R(13) R(15) R(26) R(6)
    /* x0 += ks0 (=0) */ x1 += ks1 + 3u;
    R(17) R(29) R(16) R(24)
    x0 += ks1;  x1 += ks2 + 4u;
    R(13) R(15) R(26) R(6)
    x0 += ks2;  x1 += 5u;                 // ks0 + 5
#undef R
    return x0 ^ x1;
}

// ---------- fast gumbel: -log(-log(u)) via MUFU.LG2 + near-1 log1p poly ----
// (verified: zero argmax flips vs the reference)
__device__ __forceinline__ float gumbel_fast(uint32_t bits) {
    float u = __uint_as_float((bits >> 9) | 0x3f800000u) - 1.0f;
    u = fmaxf(u, 1e-20f);
    const float LN2 = 0.69314718055994530942f;
    float nl_m = __log2f(u) * -LN2;
    float s = u - 1.0f;                       // exact for u in [0.5,1]
    float p = fmaf(s, -1.0f / 6.0f, 1.0f / 5.0f);
    p = fmaf(p, s, -0.25f);
    p = fmaf(p, s, 1.0f / 3.0f);
    p = fmaf(p, s, -0.5f);
    p = fmaf(p, s, 1.0f);
    float nl_p = -s * p;
    float nl = (s > -0.08f) ? nl_p : nl_m;
    return __log2f(nl) * -LN2;
}

__device__ __forceinline__ float argmax_pick(float2 v0, float2 v1, float rt,
                                             uint32_t r0, uint32_t r1,
                                             uint32_t r2, uint32_t r3) {
    float zb = fmaf(v0.x, rt, gumbel_fast(r0));
    float xb = v0.x;
    float z;
    z = fmaf(v0.y, rt, gumbel_fast(r1)); if (z > zb) { zb = z; xb = v0.y; }
    z = fmaf(v1.x, rt, gumbel_fast(r2)); if (z > zb) { zb = z; xb = v1.x; }
    z = fmaf(v1.y, rt, gumbel_fast(r3)); if (z > zb) { zb = z; xb = v1.y; }
    return xb;
}

__global__ __launch_bounds__(256)
void tdgs_pool_kernel(const float* __restrict__ x,
                      const float* __restrict__ temp,
                      float* __restrict__ out) {
    unsigned p = blockIdx.x * 256u + threadIdx.x;   // pair index, b in [0,16)
    unsigned wo = p % 56u;
    unsigned t1 = p / 56u;
    unsigned ho = t1 % 56u;
    unsigned t2 = t1 / 56u;          // b*128 + c, b < 16
    unsigned c  = t2 % 128u;

    // temperature: relu + 0.1 -> one reciprocal, shared by both outputs
    float T  = temp[(c * 56u + ho) * 56u + wo];
    float tt = fmaxf(T, 0.0f) + 0.1f;
    float rt = __frcp_rn(tt);

    // x patches (2x2, row-major within patch) for b and b+16
    unsigned xoff = (t2 * 112u + 2u * ho) * 112u + 2u * wo;
    float2 a0 = *reinterpret_cast<const float2*>(x + xoff);
    float2 a1 = *reinterpret_cast<const float2*>(x + xoff + 112u);
    float2 b0 = *reinterpret_cast<const float2*>(x + xoff + HALF_CNT);
    float2 b1 = *reinterpret_cast<const float2*>(x + xoff + HALF_CNT + 112u);

    // 8 independent hashes; counters 4p+k and 4p+k+HALF_CNT
    unsigned base = p * 4u;
    uint32_t r0a = tf_xor_0_42(base + 0u);
    uint32_t r1a = tf_xor_0_42(base + 1u);
    uint32_t r2a = tf_xor_0_42(base + 2u);
    uint32_t r3a = tf_xor_0_42(base + 3u);
    uint32_t r0b = tf_xor_0_42(base + HALF_CNT + 0u);
    uint32_t r1b = tf_xor_0_42(base + HALF_CNT + 1u);
    uint32_t r2b = tf_xor_0_42(base + HALF_CNT + 2u);
    uint32_t r3b = tf_xor_0_42(base + HALF_CNT + 3u);

    out[p]            = argmax_pick(a0, a1, rt, r0a, r1a, r2a, r3a);
    out[p + OUT_HALF] = argmax_pick(b0, b1, rt, r0b, r1b, r2b, r3b);
}

extern "C" void kernel_launch(void* const* d_in, const int* in_sizes, int n_in,
                              void* d_out, int out_size) {
    const float* x    = (const float*)d_in[0];   // (32,128,112,112) fp32
    const float* temp = (const float*)d_in[1];   // (128,56,56) fp32
    float* out        = (float*)d_out;           // (32,128,56,56) fp32

    // pairs = 16*128*56*56 = 6,422,528 = 256 * 25088 exactly
    tdgs_pool_kernel<<<25088, 256>>>(x, temp, out);
}

// round 7
// speedup vs baseline: 2.0292x; 2.0292x over previous
#include <cuda_runtime.h>
#include <stdint.h>

// TDGSPooling2d: gumbel-softmax hard pooling over 2x2 patches (forward = argmax).
// out[b,c,ho,wo] = x_patch[argmax_k(x_patch[k]/temp[c,ho,wo] + g_k)]
// Noise: JAX partitionable threefry: bits[i] = o0^o1,
//   (o0,o1) = threefry2x32(key=(0,42), counter=(0,i))
//
// R7: R6 with the counter-stride bug fixed. Noise flat index for output o is
// 4*o + k; per batch-quarter (8 batches) the output stride is QO, so the
// COUNTER stride is 4*QO == QC (equal to the x element stride by coincidence:
// x has 4x the elements of out). R6 used q*(QC*4) — 4x over-stride.

#define QC 12845056u   // x element stride AND counter stride per quarter (=4*QO)
#define QO 3211264u    // output element stride per batch-quarter (8*401408)

// add on the FMA pipe: a*one + b, one==1 but unprovable by ptxas
__device__ __forceinline__ uint32_t addf(uint32_t a, uint32_t b, uint32_t one) {
    uint32_t r;
    asm("mad.lo.u32 %0, %1, %2, %3;" : "=r"(r) : "r"(a), "r"(one), "r"(b));
    return r;
}

__device__ __forceinline__ uint32_t rotl(uint32_t v, int r) {
    return __funnelshift_l(v, v, r);
}

// ---------- threefry2x32, key=(0,42), counter (0,c1), return o0^o1 ----------
// ks0 = 0, ks1 = 42, ks2 = 0x1BD11BDA ^ 0 ^ 42 = 0x1BD11BF0
__device__ __forceinline__ uint32_t tf_xor_0_42(uint32_t c1, uint32_t one) {
    const uint32_t ks1 = 42u;
    const uint32_t ks2 = 0x1BD11BF0u;
    uint32_t x1 = addf(c1, ks1, one);
    uint32_t x0 = x1;                 // round-1 add with x0 = c0+ks0 = 0
    x1 = rotl(x1, 13) ^ x0;
#define R(r) { x0 = addf(x1, x0, one); x1 = rotl(x1, (r)) ^ x0; }
    R(15) R(26) R(6)
    x0 = addf(x0, ks1, one);      x1 = addf(x1, ks2 + 1u, one);
    R(17) R(29) R(16) R(24)
    x0 = addf(x0, ks2, one);      x1 = addf(x1, 2u, one);        // ks0+2
    R(13) R(15) R(26) R(6)
    /* x0 += ks0 (=0) */          x1 = addf(x1, ks1 + 3u, one);
    R(17) R(29) R(16) R(24)
    x0 = addf(x0, ks1, one);      x1 = addf(x1, ks2 + 4u, one);
    R(13) R(15) R(26) R(6)
    x0 = addf(x0, ks2, one);      x1 = addf(x1, 5u, one);        // ks0+5
#undef R
    return x0 ^ x1;
}

// ---------- fast gumbel: -log(-log(u)) ----------
// m = bits>>9 (<= 2^23), u = m*2^-23 exactly:
//   bf = (float)m                       (I2F, exact)
//   log2(u) = log2(bf) - 23
//   s = u-1 = fmaf(bf, 2^-23, -1)       (exact, same float as u-1)
// MUFU path for s <= -0.08; log1p polynomial for s in (-0.08, 0] where
// MUFU's absolute error would blow up -log(u). No u=0 clamp: g -> -inf
// there (never wins), reference's clamped g = -3.83 also never wins
// (P(other three gumbels all below -3.83) ~ 1e-60). Argmax unchanged.
__device__ __forceinline__ float gumbel_fast(uint32_t bits) {
    const float LN2 = 0.69314718055994530942f;
    float bf = (float)(bits >> 9);
    float nl_m = fmaf(__log2f(bf), -LN2, 23.0f * LN2);
    float s = fmaf(bf, 0x1p-23f, -1.0f);
    float p = fmaf(s, -1.0f / 6.0f, 1.0f / 5.0f);
    p = fmaf(p, s, -0.25f);
    p = fmaf(p, s, 1.0f / 3.0f);
    p = fmaf(p, s, -0.5f);
    p = fmaf(p, s, 1.0f);
    float nl_p = -s * p;
    float nl = (s > -0.08f) ? nl_p : nl_m;
    return __log2f(nl) * -LN2;
}

__device__ __forceinline__ float argmax_pick(float2 v0, float2 v1, float rt,
                                             uint32_t r0, uint32_t r1,
                                             uint32_t r2, uint32_t r3) {
    float zb = fmaf(v0.x, rt, gumbel_fast(r0));
    float xb = v0.x;
    float z;
    z = fmaf(v0.y, rt, gumbel_fast(r1)); if (z > zb) { zb = z; xb = v0.y; }
    z = fmaf(v1.x, rt, gumbel_fast(r2)); if (z > zb) { zb = z; xb = v1.x; }
    z = fmaf(v1.y, rt, gumbel_fast(r3)); if (z > zb) { zb = z; xb = v1.y; }
    return xb;
}

__global__ __launch_bounds__(256)
void tdgs_pool_kernel(const float* __restrict__ x,
                      const float* __restrict__ temp,
                      float* __restrict__ out) {
    uint32_t one = gridDim.y;                       // == 1, opaque to ptxas
    unsigned p = blockIdx.x * 256u + threadIdx.x;   // index over b in [0,8)
    unsigned wo = p % 56u;
    unsigned t1 = p / 56u;
    unsigned ho = t1 % 56u;
    unsigned t2 = t1 / 56u;          // b*128 + c, b < 8
    unsigned c  = t2 % 128u;

    // temperature: relu + 0.1 -> one reciprocal shared by all 4 outputs
    float T  = temp[(c * 56u + ho) * 56u + wo];
    float tt = fmaxf(T, 0.0f) + 0.1f;
    float rt = __frcp_rn(tt);

    unsigned xoff = (t2 * 112u + 2u * ho) * 112u + 2u * wo;
    unsigned base = p * 4u;

    #pragma unroll
    for (unsigned q = 0; q < 4; q++) {
        unsigned xo = xoff + q * QC;
        float2 v0 = *reinterpret_cast<const float2*>(x + xo);
        float2 v1 = *reinterpret_cast<const float2*>(x + xo + 112u);
        unsigned cb = base + q * QC;          // counter stride = 4*QO = QC
        uint32_t r0 = tf_xor_0_42(cb + 0u, one);
        uint32_t r1 = tf_xor_0_42(cb + 1u, one);
        uint32_t r2 = tf_xor_0_42(cb + 2u, one);
        uint32_t r3 = tf_xor_0_42(cb + 3u, one);
        out[p + q * QO] = argmax_pick(v0, v1, rt, r0, r1, r2, r3);
    }
}

extern "C" void kernel_launch(void* const* d_in, const int* in_sizes, int n_in,
                              void* d_out, int out_size) {
    const float* x    = (const float*)d_in[0];   // (32,128,112,112) fp32
    const float* temp = (const float*)d_in[1];   // (128,56,56) fp32
    float* out        = (float*)d_out;           // (32,128,56,56) fp32

    // quads = 8*128*56*56 = 3,211,264 = 256 * 12544 exactly
    tdgs_pool_kernel<<<12544, 256>>>(x, temp, out);
}